// round 4
// baseline (speedup 1.0000x reference)
#include <cuda_runtime.h>
#include <cuda_bf16.h>
#include <cstdint>

// BNB 8-bit embedding dequant-on-gather, 256-bit memory ops (sm_103a).
// Identities: row base = q_idx + id*1024; scale = absmax[id>>2].
//
// Layout: 8 tokens/CTA, 256 threads. CTA splits into two 128-thread halves;
// each half covers 4 token rows, one 32B segment per thread per token.
// Per thread: 4 independent LDG.256 + 4 STG.256 (half the instruction count
// of the int4 version; same bytes).

#define TOKENS_PER_CTA 8

__device__ __forceinline__ void ldg_nc_v8(const int* p, uint32_t r[8]) {
    asm volatile("ld.global.nc.v8.b32 {%0,%1,%2,%3,%4,%5,%6,%7}, [%8];"
                 : "=r"(r[0]), "=r"(r[1]), "=r"(r[2]), "=r"(r[3]),
                   "=r"(r[4]), "=r"(r[5]), "=r"(r[6]), "=r"(r[7])
                 : "l"(p));
}

__device__ __forceinline__ void stg_cs_v8(float* p, const float o[8]) {
    asm volatile("st.global.cs.v8.f32 [%0], {%1,%2,%3,%4,%5,%6,%7,%8};"
                 :: "l"(p),
                    "f"(o[0]), "f"(o[1]), "f"(o[2]), "f"(o[3]),
                    "f"(o[4]), "f"(o[5]), "f"(o[6]), "f"(o[7])
                 : "memory");
}

__global__ __launch_bounds__(256)
void bnb8bit_embedding_kernel(const int* __restrict__ x,
                              const int* __restrict__ q_idx,
                              const float* __restrict__ absmax,
                              const float* __restrict__ code,
                              float* __restrict__ out,
                              int n_tokens) {
    __shared__ float s_code[256];
    __shared__ int   s_ids[TOKENS_PER_CTA];

    const int t = threadIdx.x;
    s_code[t] = code[t];

    const int base = blockIdx.x * TOKENS_PER_CTA;
    if (t < TOKENS_PER_CTA) {
        int tok = base + t;
        s_ids[t] = (tok < n_tokens) ? x[tok] : 0;
    }
    __syncthreads();

    const int half = t >> 7;        // 0 or 1: which group of 4 tokens
    const int lane = t & 127;       // 32B segment within the row
    const int toff = half * 4;

    if (base + TOKENS_PER_CTA <= n_tokens) {
        uint32_t v[4][8];
        float    sc[4];
        #pragma unroll
        for (int i = 0; i < 4; i++) {
            const int id = s_ids[toff + i];
            sc[i] = __ldg(absmax + (id >> 2));
            ldg_nc_v8(q_idx + (size_t)id * 1024 + lane * 8, v[i]);
        }
        #pragma unroll
        for (int i = 0; i < 4; i++) {
            float o[8];
            #pragma unroll
            for (int j = 0; j < 8; j++)
                o[j] = s_code[v[i][j]] * sc[i];
            stg_cs_v8(out + (size_t)(base + toff + i) * 1024 + lane * 8, o);
        }
    } else {
        // Tail: per-token, same 256-bit path with bounds check.
        for (int i = 0; i < 4; i++) {
            const int tok = base + toff + i;
            if (tok >= n_tokens) break;
            const int id = s_ids[toff + i];
            const float sc = __ldg(absmax + (id >> 2));
            uint32_t v[8];
            ldg_nc_v8(q_idx + (size_t)id * 1024 + lane * 8, v);
            float o[8];
            #pragma unroll
            for (int j = 0; j < 8; j++)
                o[j] = s_code[v[j]] * sc;
            stg_cs_v8(out + (size_t)tok * 1024 + lane * 8, o);
        }
    }
}

extern "C" void kernel_launch(void* const* d_in, const int* in_sizes, int n_in,
                              void* d_out, int out_size) {
    const int*   x      = (const int*)d_in[0];
    const int*   q_idx  = (const int*)d_in[1];
    const float* absmax = (const float*)d_in[2];
    const float* code   = (const float*)d_in[3];
    float*       out    = (float*)d_out;

    const int n_tokens = in_sizes[0];   // 8*4096 = 32768
    const int grid = (n_tokens + TOKENS_PER_CTA - 1) / TOKENS_PER_CTA;
    bnb8bit_embedding_kernel<<<grid, 256>>>(x, q_idx, absmax, code, out, n_tokens);
}